// round 16
// baseline (speedup 1.0000x reference)
#include <cuda_runtime.h>
#include <cuda_fp16.h>
#include <cstdint>

#define N_NODES 500000
#define N_EDGES 2000000
#define C       32
#define NGRAPH  1024
#define HIDDEN  1024
#define LAYERS  8

#define SCAN_BLK 256
#define ITEMS    8
#define CHUNK    (SCAN_BLK * ITEMS)                       // 2048
#define NBLK     ((N_NODES + CHUNK - 1) / CHUNK)          // 245

// ---------------- device scratch (static; zero-initialized at load) ----------
__device__ __half d_xh  [2][(size_t)N_NODES * C];         // fp16 feature ping/pong
__device__ int    d_cnt [2][N_NODES];                     // degrees (self-cleaned by k_scan)
__device__ int    d_cur [2][N_NODES];                     // scatter cursors
__device__ int    d_csr [2][N_EDGES];
__device__ int4   d_meta[N_NODES];                        // {b0, d0, b1, d1}
__device__ int    d_agg [2][NBLK];                        // scan block aggregates
__device__ int    d_flag[2][NBLK];                        // publish flags (reset by k_hist)
__device__ float  d_gsum[NGRAPH * C];                     // self-cleaned by k_mlp
__device__ float  d_gcnt[NGRAPH];

// ---------------- degree histogram + scan-flag reset ---------------------------
__global__ void k_hist(const int* __restrict__ src, const int* __restrict__ dst, int E)
{
    int e = blockIdx.x * blockDim.x + threadIdx.x;
    if (e < 2 * NBLK) ((int*)d_flag)[e] = 0;    // reset flags for this call's k_scan
    if (e >= E) return;
    atomicAdd(&d_cnt[0][__ldg(dst + e)], 1);
    atomicAdd(&d_cnt[1][__ldg(src + e)], 1);
}

// ---------------- single-pass scan: publish aggregate, lookback, write meta ----
__global__ void k_scan()
{
    int y   = blockIdx.y;
    int bid = blockIdx.x;
    int tid = threadIdx.x;
    int lane = tid & 31, warp = tid >> 5;
    int base_i = bid * CHUNK + tid * ITEMS;

    int v[ITEMS]; int tsum = 0;
    #pragma unroll
    for (int j = 0; j < ITEMS; j++) {
        int i = base_i + j;
        v[j] = (i < N_NODES) ? d_cnt[y][i] : 0;
        tsum += v[j];
    }
    int incl = tsum;
    #pragma unroll
    for (int o = 1; o < 32; o <<= 1) {
        int t = __shfl_up_sync(0xffffffffu, incl, o);
        if (lane >= o) incl += t;
    }
    __shared__ int shw[8];
    __shared__ int s_tot;
    if (lane == 31) shw[warp] = incl;
    __syncthreads();
    if (warp == 0 && lane < 8) {
        int b = shw[lane], ib = b;
        #pragma unroll
        for (int o = 1; o < 8; o <<= 1) {
            int t = __shfl_up_sync(0xffu, ib, o);
            if (lane >= o) ib += t;
        }
        shw[lane] = ib - b;                     // exclusive warp base
        if (lane == 7) s_tot = ib;              // block total
    }
    __syncthreads();

    if (tid == 0) {
        d_agg[y][bid] = s_tot;
        __threadfence();
        d_flag[y][bid] = 1;
    }

    __shared__ int s_red[SCAN_BLK];
    int a = 0;
    if (tid < bid) {
        volatile int* fl = &d_flag[y][0];
        while (fl[tid] == 0) { }
        __threadfence();
        a = *((volatile int*)&d_agg[y][tid]);
    }
    s_red[tid] = a;
    __syncthreads();
    #pragma unroll
    for (int o = SCAN_BLK / 2; o > 0; o >>= 1) {
        if (tid < o) s_red[tid] += s_red[tid + o];
        __syncthreads();
    }
    int run = s_red[0] + shw[warp] + (incl - tsum);

    #pragma unroll
    for (int j = 0; j < ITEMS; j++) {
        int i = base_i + j;
        if (i < N_NODES) {
            int* mp = (int*)&d_meta[i];
            mp[y * 2 + 0] = run;          // base
            mp[y * 2 + 1] = v[j];         // degree
            d_cur[y][i]   = run;
            d_cnt[y][i]   = 0;            // self-clean for next call
            run += v[j];
        }
    }
}

// ---------------- fused CSR fill + feature init --------------------------------
__global__ void k_scatter_init(const int* __restrict__ src, const int* __restrict__ dst,
                               const int* __restrict__ nodes, const float* __restrict__ emb,
                               int E, int n)
{
    int idx = blockIdx.x * blockDim.x + threadIdx.x;
    if (idx < n * C) {
        int node = idx >> 5;
        int c    = idx & 31;
        int t    = __ldg(nodes + node);
        d_xh[0][idx] = __float2half_rn(__ldg(emb + t * C + c));
    }
    if (idx < E) {
        int s = __ldg(src + idx);
        int t = __ldg(dst + idx);
        int p = atomicAdd(&d_cur[0][t], 1);  d_csr[0][p] = s;
        int q = atomicAdd(&d_cur[1][s], 1);  d_csr[1][q] = t;
    }
}

// ---------------- mma.m16n8k16 helper -------------------------------------------
__device__ __forceinline__ void mma_16816(float* d,
                                          uint32_t a0, uint32_t a1, uint32_t a2, uint32_t a3,
                                          uint32_t b0, uint32_t b1)
{
    asm volatile(
        "mma.sync.aligned.m16n8k16.row.col.f32.f16.f16.f32 "
        "{%0,%1,%2,%3}, {%4,%5,%6,%7}, {%8,%9}, {%0,%1,%2,%3};"
        : "+f"(d[0]), "+f"(d[1]), "+f"(d[2]), "+f"(d[3])
        : "r"(a0), "r"(a1), "r"(a2), "r"(a3), "r"(b0), "r"(b1));
}

#define CAPI 512

// ---- gather: lane = (n2 = lane>>2 node-in-octet, c4 = lane&3 16B chunk) --------
// One LDG.128 fetches one neighbor row for 8 nodes. Per-node fp32 accumulators
// live in the node's own 4 lanes (8 floats each); HADD2 pairwise pre-sum.
template<bool FAST>
__device__ __forceinline__ void gather_pass(
    int nl, const __half* __restrict__ xin,
    const int4* s_meta, int beg0, int beg1, const int (*s_idx)[CAPI],
    int c4, const __half (*s_x)[32],
    __half (*s_h0)[32], __half (*s_h1)[32])
{
    const unsigned FULL = 0xffffffffu;
    const int4 m = s_meta[nl];
    const int o0 = m.x - beg0, dg0 = m.y;
    const int o1 = m.z - beg1, dg1 = m.w;

    // seed with residual (16 B of this node's row)
    uint4 xr = *(const uint4*)&s_x[nl][c4 * 8];
    float f[8], g[8];
    {
        float2 t;
        t = __half22float2(*(__half2*)&xr.x); f[0] = t.x; f[1] = t.y;
        t = __half22float2(*(__half2*)&xr.y); f[2] = t.x; f[3] = t.y;
        t = __half22float2(*(__half2*)&xr.z); f[4] = t.x; f[5] = t.y;
        t = __half22float2(*(__half2*)&xr.w); f[6] = t.x; f[7] = t.y;
        #pragma unroll
        for (int k = 0; k < 8; k++) g[k] = f[k];
    }

    const int jm = max(__reduce_max_sync(FULL, (unsigned)dg0),
                       __reduce_max_sync(FULL, (unsigned)dg1));

    const uint4 z4 = make_uint4(0u, 0u, 0u, 0u);
    int j = 0;
    for (; j + 2 <= jm; j += 2) {
        uint4 v0a = z4, v0b = z4, v1a = z4, v1b = z4;
        if (j < dg0) {
            int p = o0 + j;
            int s = FAST ? s_idx[0][p] : ((p < CAPI) ? s_idx[0][p] : __ldg(&d_csr[0][beg0 + p]));
            v0a = __ldg((const uint4*)(xin + (size_t)s * C) + c4);
        }
        if (j + 1 < dg0) {
            int p = o0 + j + 1;
            int s = FAST ? s_idx[0][p] : ((p < CAPI) ? s_idx[0][p] : __ldg(&d_csr[0][beg0 + p]));
            v0b = __ldg((const uint4*)(xin + (size_t)s * C) + c4);
        }
        if (j < dg1) {
            int p = o1 + j;
            int s = FAST ? s_idx[1][p] : ((p < CAPI) ? s_idx[1][p] : __ldg(&d_csr[1][beg1 + p]));
            v1a = __ldg((const uint4*)(xin + (size_t)s * C) + c4);
        }
        if (j + 1 < dg1) {
            int p = o1 + j + 1;
            int s = FAST ? s_idx[1][p] : ((p < CAPI) ? s_idx[1][p] : __ldg(&d_csr[1][beg1 + p]));
            v1b = __ldg((const uint4*)(xin + (size_t)s * C) + c4);
        }
        // pairwise fp16 add, single convert, fp32 accumulate
        __half2 pa; float2 t;
        pa = __hadd2(*(__half2*)&v0a.x, *(__half2*)&v0b.x); t = __half22float2(pa); f[0] += t.x; f[1] += t.y;
        pa = __hadd2(*(__half2*)&v0a.y, *(__half2*)&v0b.y); t = __half22float2(pa); f[2] += t.x; f[3] += t.y;
        pa = __hadd2(*(__half2*)&v0a.z, *(__half2*)&v0b.z); t = __half22float2(pa); f[4] += t.x; f[5] += t.y;
        pa = __hadd2(*(__half2*)&v0a.w, *(__half2*)&v0b.w); t = __half22float2(pa); f[6] += t.x; f[7] += t.y;
        pa = __hadd2(*(__half2*)&v1a.x, *(__half2*)&v1b.x); t = __half22float2(pa); g[0] += t.x; g[1] += t.y;
        pa = __hadd2(*(__half2*)&v1a.y, *(__half2*)&v1b.y); t = __half22float2(pa); g[2] += t.x; g[3] += t.y;
        pa = __hadd2(*(__half2*)&v1a.z, *(__half2*)&v1b.z); t = __half22float2(pa); g[4] += t.x; g[5] += t.y;
        pa = __hadd2(*(__half2*)&v1a.w, *(__half2*)&v1b.w); t = __half22float2(pa); g[6] += t.x; g[7] += t.y;
    }
    if (j < jm) {
        uint4 v0 = z4, v1 = z4;
        if (j < dg0) {
            int p = o0 + j;
            int s = FAST ? s_idx[0][p] : ((p < CAPI) ? s_idx[0][p] : __ldg(&d_csr[0][beg0 + p]));
            v0 = __ldg((const uint4*)(xin + (size_t)s * C) + c4);
        }
        if (j < dg1) {
            int p = o1 + j;
            int s = FAST ? s_idx[1][p] : ((p < CAPI) ? s_idx[1][p] : __ldg(&d_csr[1][beg1 + p]));
            v1 = __ldg((const uint4*)(xin + (size_t)s * C) + c4);
        }
        float2 t;
        t = __half22float2(*(__half2*)&v0.x); f[0] += t.x; f[1] += t.y;
        t = __half22float2(*(__half2*)&v0.y); f[2] += t.x; f[3] += t.y;
        t = __half22float2(*(__half2*)&v0.z); f[4] += t.x; f[5] += t.y;
        t = __half22float2(*(__half2*)&v0.w); f[6] += t.x; f[7] += t.y;
        t = __half22float2(*(__half2*)&v1.x); g[0] += t.x; g[1] += t.y;
        t = __half22float2(*(__half2*)&v1.y); g[2] += t.x; g[3] += t.y;
        t = __half22float2(*(__half2*)&v1.z); g[4] += t.x; g[5] += t.y;
        t = __half22float2(*(__half2*)&v1.w); g[6] += t.x; g[7] += t.y;
    }

    const float nf = __fdividef(1.f, 1.f + (float)dg0);
    const float nb = __fdividef(1.f, 1.f + (float)dg1);

    uint4 pf, pb;
    {
        __half2 h;
        h = __floats2half2_rn(f[0] * nf, f[1] * nf); pf.x = *(uint32_t*)&h;
        h = __floats2half2_rn(f[2] * nf, f[3] * nf); pf.y = *(uint32_t*)&h;
        h = __floats2half2_rn(f[4] * nf, f[5] * nf); pf.z = *(uint32_t*)&h;
        h = __floats2half2_rn(f[6] * nf, f[7] * nf); pf.w = *(uint32_t*)&h;
        h = __floats2half2_rn(g[0] * nb, g[1] * nb); pb.x = *(uint32_t*)&h;
        h = __floats2half2_rn(g[2] * nb, g[3] * nb); pb.y = *(uint32_t*)&h;
        h = __floats2half2_rn(g[4] * nb, g[5] * nb); pb.z = *(uint32_t*)&h;
        h = __floats2half2_rn(g[6] * nb, g[7] * nb); pb.w = *(uint32_t*)&h;
    }
    *(uint4*)&s_h0[nl][c4 * 8] = pf;
    *(uint4*)&s_h1[nl][c4 * 8] = pb;
}

// ---------------- fused layer: octet gather (single pass) -> mma ---------------
// 256 threads = 8 warps; 64 nodes/block; warp handles 8 nodes in ONE pass.
__global__ void __launch_bounds__(256) k_layer(const __half* __restrict__ xin,
                                               __half* __restrict__ xout,
                                               const float* __restrict__ w, int n)
{
    __shared__ __half s_wt[2][32][32];   // 4 KB transposed weights
    __shared__ __half s_h [2][64][32];   // 8 KB aggregated features
    __shared__ __half s_x [64][32];      // 4 KB residual (block-staged)
    __shared__ int4   s_meta[64];        // 1 KB node meta
    __shared__ int    s_idx[2][CAPI];    // 4 KB CSR slices

    const int tid  = threadIdx.x;
    const int lane = tid & 31;
    const int warp = tid >> 5;
    const int n2   = lane >> 2;           // node in octet 0..7
    const int c4   = lane & 3;            // 16B chunk 0..3
    const int blockBase = blockIdx.x * 64;
    const int lastLocal = min(64, n - blockBase);

    for (int i = tid; i < 2 * 32 * 32; i += 256) {
        int d = i >> 10, rem = i & 1023, k = rem >> 5, j = rem & 31;
        s_wt[d][j][k] = __float2half_rn(__ldg(w + d * 1024 + k * 32 + j));
    }
    if (tid < 64) {
        s_meta[tid] = (tid < lastLocal) ? __ldg(&d_meta[blockBase + tid])
                                        : make_int4(0, 0, 0, 0);
    }
    // stage residual rows: 64 rows x 64 B = 4 KB, one uint4 per thread (coalesced)
    {
        int i = tid * 8;                              // halves
        uint4 val = make_uint4(0u, 0u, 0u, 0u);
        if (i < lastLocal * C)
            val = *(const uint4*)(xin + (size_t)blockBase * C + i);
        *(uint4*)&(((__half*)s_x)[i]) = val;
    }
    __syncthreads();

    const int4 mF = s_meta[0];
    const int4 mL = s_meta[lastLocal - 1];
    const int beg0 = mF.x, len0 = mL.x + mL.y - mF.x;
    const int beg1 = mF.z, len1 = mL.z + mL.w - mF.z;
    for (int i = tid; i < min(len0, CAPI); i += 256) s_idx[0][i] = __ldg(&d_csr[0][beg0 + i]);
    for (int i = tid; i < min(len1, CAPI); i += 256) s_idx[1][i] = __ldg(&d_csr[1][beg1 + i]);
    __syncthreads();

    const bool fastI = (len0 <= CAPI) && (len1 <= CAPI);
    const int  nl    = warp * 8 + n2;

    if (fastI)
        gather_pass<true >(nl, xin, s_meta, beg0, beg1, s_idx, c4, s_x, s_h[0], s_h[1]);
    else
        gather_pass<false>(nl, xin, s_meta, beg0, beg1, s_idx, c4, s_x, s_h[0], s_h[1]);
    __syncthreads();

    // ---- GEMM + epilogue: warps 0..3, warp = m-tile (16 nodes), both dirs ----
    if (warp < 4) {
        const int g  = lane >> 2;
        const int t  = lane & 3;
        const int m0 = warp * 16;

        float acc0[4][4], acc1[4][4];
        #pragma unroll
        for (int nt = 0; nt < 4; nt++)
            #pragma unroll
            for (int i = 0; i < 4; i++) { acc0[nt][i] = 0.f; acc1[nt][i] = 0.f; }

        #pragma unroll
        for (int kt = 0; kt < 32; kt += 16) {
            uint32_t a0 = *(const uint32_t*)&s_h[0][m0 + g    ][kt + t * 2];
            uint32_t a1 = *(const uint32_t*)&s_h[0][m0 + g + 8][kt + t * 2];
            uint32_t a2 = *(const uint32_t*)&s_h[0][m0 + g    ][kt + t * 2 + 8];
            uint32_t a3 = *(const uint32_t*)&s_h[0][m0 + g + 8][kt + t * 2 + 8];
            #pragma unroll
            for (int nt = 0; nt < 4; nt++) {
                uint32_t b0 = *(const uint32_t*)&s_wt[0][nt * 8 + g][kt + t * 2];
                uint32_t b1 = *(const uint32_t*)&s_wt[0][nt * 8 + g][kt + t * 2 + 8];
                mma_16816(acc0[nt], a0, a1, a2, a3, b0, b1);
            }
            a0 = *(const uint32_t*)&s_h[1][m0 + g    ][kt + t * 2];
            a1 = *(const uint32_t*)&s_h[1][m0 + g + 8][kt + t * 2];
            a2 = *(const uint32_t*)&s_h[1][m0 + g    ][kt + t * 2 + 8];
            a3 = *(const uint32_t*)&s_h[1][m0 + g + 8][kt + t * 2 + 8];
            #pragma unroll
            for (int nt = 0; nt < 4; nt++) {
                uint32_t b0 = *(const uint32_t*)&s_wt[1][nt * 8 + g][kt + t * 2];
                uint32_t b1 = *(const uint32_t*)&s_wt[1][nt * 8 + g][kt + t * 2 + 8];
                mma_16816(acc1[nt], a0, a1, a2, a3, b0, b1);
            }
        }

        int node0 = blockBase + m0 + g;
        int node1 = node0 + 8;
        #pragma unroll
        for (int nt = 0; nt < 4; nt++) {
            int col = nt * 8 + t * 2;
            float2 xv0 = __half22float2(*(__half2*)&s_x[m0 + g    ][col]);
            float2 xv1 = __half22float2(*(__half2*)&s_x[m0 + g + 8][col]);
            float o00 = xv0.x + fmaxf(acc0[nt][0], 0.f) + fmaxf(acc1[nt][0], 0.f);
            float o01 = xv0.y + fmaxf(acc0[nt][1], 0.f) + fmaxf(acc1[nt][1], 0.f);
            float o10 = xv1.x + fmaxf(acc0[nt][2], 0.f) + fmaxf(acc1[nt][2], 0.f);
            float o11 = xv1.y + fmaxf(acc0[nt][3], 0.f) + fmaxf(acc1[nt][3], 0.f);
            if (node0 < n)
                *(__half2*)&xout[(size_t)node0 * C + col] = __floats2half2_rn(o00, o01);
            if (node1 < n)
                *(__half2*)&xout[(size_t)node1 * C + col] = __floats2half2_rn(o10, o11);
        }
    }
}

// ---------------- pooling: per-graph sum + count (batch sorted) ----------------
__global__ void k_pool(const int* __restrict__ batch, const __half* __restrict__ x, int n)
{
    int lane = threadIdx.x & 31;
    int warp = threadIdx.x >> 5;
    int base = blockIdx.x * 256 + warp * 32;

    float acc = 0.f;
    int cur = -1, run = 0;
    for (int j = 0; j < 32; j++) {
        int node = base + j;
        if (node >= n) break;
        int b = __ldg(batch + node);
        float v = __half2float(__ldg(x + (size_t)node * C + lane));
        if (b != cur) {
            if (cur >= 0) {
                atomicAdd(&d_gsum[cur * C + lane], acc);
                if (lane == 0) atomicAdd(&d_gcnt[cur], (float)run);
            }
            cur = b; acc = 0.f; run = 0;
        }
        acc += v; run++;
    }
    if (cur >= 0) {
        atomicAdd(&d_gsum[cur * C + lane], acc);
        if (lane == 0) atomicAdd(&d_gcnt[cur], (float)run);
    }
}

// ---------------- MLP head: 8 graphs per block; self-cleans pool buffers -------
#define GPB 8
__global__ void k_mlp(const float* __restrict__ hw, const float* __restrict__ hb,
                      const float* __restrict__ ow, float* __restrict__ out)
{
    __shared__ float gs[GPB][C];
    __shared__ float sout[GPB];
    int tid = threadIdx.x;
    if (tid < GPB * C) {
        int g = tid >> 5, c = tid & 31;
        int gb = blockIdx.x * GPB + g;
        gs[g][c] = d_gsum[gb * C + c] / d_gcnt[gb];
    }
    if (tid < GPB) sout[tid] = 0.f;
    __syncthreads();
    if (tid < GPB * C) {
        int g = tid >> 5, c = tid & 31;
        d_gsum[(blockIdx.x * GPB + g) * C + c] = 0.f;
    }
    if (tid < GPB) d_gcnt[blockIdx.x * GPB + tid] = 0.f;

    float part[GPB];
    #pragma unroll
    for (int g = 0; g < GPB; g++) part[g] = 0.f;

    for (int j = tid; j < HIDDEN; j += 256) {
        float h[GPB];
        float bj = __ldg(hb + j);
        #pragma unroll
        for (int g = 0; g < GPB; g++) h[g] = bj;
        #pragma unroll
        for (int k = 0; k < C; k++) {
            float wkj = __ldg(hw + k * HIDDEN + j);
            #pragma unroll
            for (int g = 0; g < GPB; g++)
                h[g] = fmaf(gs[g][k], wkj, h[g]);
        }
        float oj = __ldg(ow + j);
        #pragma unroll
        for (int g = 0; g < GPB; g++)
            part[g] += fmaxf(h[g], 0.f) * oj;
    }
    #pragma unroll
    for (int g = 0; g < GPB; g++) {
        float v = part[g];
        #pragma unroll
        for (int off = 16; off > 0; off >>= 1)
            v += __shfl_down_sync(0xffffffffu, v, off);
        if ((tid & 31) == 0) atomicAdd(&sout[g], v);
    }
    __syncthreads();
    if (tid < GPB) out[blockIdx.x * GPB + tid] = sout[tid];
}

// ---------------- launch ---------------------------------------------------------
extern "C" void kernel_launch(void* const* d_in, const int* in_sizes, int n_in,
                              void* d_out, int out_size)
{
    const int*   nodes    = (const int*)  d_in[0];
    const int*   sources  = (const int*)  d_in[1];
    const int*   targets  = (const int*)  d_in[2];
    const int*   batch    = (const int*)  d_in[3];
    const float* emb      = (const float*)d_in[4];
    const float* conv_w   = (const float*)d_in[5];
    const float* hidden_w = (const float*)d_in[6];
    const float* hidden_b = (const float*)d_in[7];
    const float* out_w    = (const float*)d_in[8];
    float*       out      = (float*)d_out;

    const int N = in_sizes[0];
    const int E = in_sizes[1];

    // CSR build: hist (+flag reset), single-pass scan, scatter+init
    k_hist        <<<(E + 255) / 256, 256>>>(sources, targets, E);
    k_scan        <<<dim3(NBLK, 2), SCAN_BLK>>>();
    k_scatter_init<<<(N * C + 255) / 256, 256>>>(sources, targets, nodes, emb, E, N);

    // 8 fused layers, ping-pong (even count -> final in buffer 0)
    const int nb = (N + 63) / 64;
    __half* xh = nullptr;
    cudaGetSymbolAddress((void**)&xh, d_xh);
    __half* xa = xh;
    __half* xb = xh + (size_t)N_NODES * C;
    for (int l = 0; l < LAYERS; l++) {
        const float* wl = conv_w + (size_t)l * 2 * C * C;
        if ((l & 1) == 0) k_layer<<<nb, 256>>>(xa, xb, wl, N);
        else              k_layer<<<nb, 256>>>(xb, xa, wl, N);
    }
    k_pool<<<(N + 255) / 256, 256>>>(batch, xa, N);

    k_mlp<<<NGRAPH / GPB, 256>>>(hidden_w, hidden_b, out_w, out);
}